// round 6
// baseline (speedup 1.0000x reference)
#include <cuda_runtime.h>
#include <cuda_fp16.h>
#include <cstdint>
#include <cstddef>

// ---------------------------------------------------------------------------
// Problem constants
// ---------------------------------------------------------------------------
#define N_TOK   8192
#define DIN     4096
#define DOUT    4096
#define S_RANK  256
#define S_CAT   512

#define BM      128
#define BK      64          // 64 fp16 = 128 bytes per row -> SW128 swizzle
#define STAGES  3

// ---------------------------------------------------------------------------
// Scratch (device globals; no runtime allocation)
// ---------------------------------------------------------------------------
__device__ __half g_xh[(size_t)N_TOK * DIN];     // fp16(x)                64 MB
__device__ __half g_B1[(size_t)S_CAT * DIN];     // sign(V)*v2*v1*u2        4 MB
__device__ __half g_B2[(size_t)DOUT * S_CAT];    // sign(U)*u1              4 MB
__device__ __half g_H [(size_t)N_TOK * S_CAT];   // H fp16                  8 MB

// ---------------------------------------------------------------------------
// Helpers
// ---------------------------------------------------------------------------
__device__ __forceinline__ uint32_t smem_u32(const void* p) {
    uint32_t a;
    asm("{ .reg .u64 t; cvta.to.shared.u64 t, %1; cvt.u32.u64 %0, t; }" : "=r"(a) : "l"(p));
    return a;
}

#define SWZ(o) ((o) ^ (((o) >> 3) & 0x70))

#define CP_ASYNC16(s, g) \
    asm volatile("cp.async.cg.shared.global [%0], [%1], 16;" :: "r"(s), "l"(g))
#define CP_COMMIT() asm volatile("cp.async.commit_group;")
#define CP_WAIT(n)  asm volatile("cp.async.wait_group %0;" :: "n"(n) : "memory")

#define LDMATRIX_X4(r0, r1, r2, r3, addr)                                     \
    asm volatile("ldmatrix.sync.aligned.m8n8.x4.shared.b16 {%0,%1,%2,%3}, [%4];" \
        : "=r"(r0), "=r"(r1), "=r"(r2), "=r"(r3) : "r"(addr))

#define MMA_16816(d, a, b0, b1)                                               \
    asm volatile("mma.sync.aligned.m16n8k16.row.col.f32.f16.f16.f32 "         \
        "{%0,%1,%2,%3}, {%4,%5,%6,%7}, {%8,%9}, {%0,%1,%2,%3};"               \
        : "+f"((d)[0]), "+f"((d)[1]), "+f"((d)[2]), "+f"((d)[3])              \
        : "r"((a)[0]), "r"((a)[1]), "r"((a)[2]), "r"((a)[3]), "r"(b0), "r"(b1))

__device__ __forceinline__ float sgn(float v) {
    return (v > 0.0f) ? 1.0f : ((v < 0.0f) ? -1.0f : 0.0f);
}

// ---------------------------------------------------------------------------
// Prep kernels
// ---------------------------------------------------------------------------
__global__ void prep_x_kernel(const float4* __restrict__ x) {
    size_t i = (size_t)blockIdx.x * blockDim.x + threadIdx.x;   // 8388608 float4
    float4 v = x[i];
    __half2* o = (__half2*)&g_xh[4 * i];
    o[0] = __floats2half2_rn(v.x, v.y);
    o[1] = __floats2half2_rn(v.z, v.w);
}

// B1[s][i] = sign(Vcat[s][i]) * v2cat[i] * v1cat[s] * u2cat[s]   (all scales folded)
__global__ void prep_B1_kernel(const float* __restrict__ V,   const float* __restrict__ VR,
                               const float* __restrict__ v2,  const float* __restrict__ v2R,
                               const float* __restrict__ v1,  const float* __restrict__ v1R,
                               const float* __restrict__ u2,  const float* __restrict__ u2R) {
    int idx = blockIdx.x * blockDim.x + threadIdx.x;   // S_CAT*DIN
    int s = idx >> 12;
    int i = idx & 4095;
    float val;
    if (s < S_RANK) val = sgn(V [(size_t)s * DIN + i]) * v2[i] * v1[s] * u2[s];
    else {
        int s2 = s - S_RANK;
        val = sgn(VR[(size_t)s2 * DIN + i]) * v2R[i] * v1R[s2] * u2R[s2];
    }
    g_B1[idx] = __float2half(val);
}

__global__ void prep_B2_kernel(const float* __restrict__ U,  const float* __restrict__ UR,
                               const float* __restrict__ u1, const float* __restrict__ u1R) {
    int idx = blockIdx.x * blockDim.x + threadIdx.x;   // DOUT*S_CAT
    int j = idx >> 9;
    int s = idx & 511;
    float val;
    if (s < S_RANK) val = sgn(U [(size_t)j * S_RANK + s]) * u1[j];
    else            val = sgn(UR[(size_t)j * S_RANK + (s - S_RANK)]) * u1R[j];
    g_B2[idx] = __float2half(val);
}

// ---------------------------------------------------------------------------
// HMMA GEMM: C[M,N] = A[M,K] @ B[N,K]^T   (fp16 in, fp32 accum)
// CTA BM x BN_, THR_ threads; warp grid 2(M) x (nwarp/2)(N); warp tile 64x32.
// Single barrier per mainloop iteration; prefetch issued before MMA.
// EPI==1: store fp16 to g_H.  EPI==2: add bias, store fp32 to out.
// ---------------------------------------------------------------------------
template <int K, int EPI, int BN_, int THR_, int MINB>
__global__ __launch_bounds__(THR_, MINB) void gemm_kernel(float* __restrict__ out,
                                                          const float* __restrict__ bias) {
    constexpr int NWARP    = THR_ / 32;
    constexpr int WN_WARPS = NWARP / 2;
    static_assert(BN_ / WN_WARPS == 32, "warp tile must be 64x32");
    constexpr int STAGE_A  = BM * 128;
    constexpr int STAGE_B  = BN_ * 128;
    constexpr int STAGE    = STAGE_A + STAGE_B;
    constexpr int NIT      = K / BK;
    constexpr int TASKS    = (BM + BN_) * 8;     // 16B-chunk loads per stage

    extern __shared__ char smem_raw[];
    const uint32_t sm_tiles = smem_u32(smem_raw);
    const int tid  = threadIdx.x;
    const int wid  = tid >> 5;
    const int lane = tid & 31;
    const int m0 = blockIdx.y * BM;
    const int n0 = blockIdx.x * BN_;

    const __half* A  = (EPI == 1) ? g_xh : g_H;
    const __half* Bp = (EPI == 1) ? g_B1 : g_B2;

    const int wm = wid / WN_WARPS;       // 0..1
    const int wn = wid % WN_WARPS;

    const int ldRow = lane & 15;
    const int ldSel = lane >> 4;
    const uint32_t aOffBase = (uint32_t)((wm * 64 + ldRow) * 128 + ldSel * 16);
    const uint32_t bOffBase = (uint32_t)((wn * 32 + ldRow) * 128 + ldSel * 16);

    float acc[4][4][4] = {};   // 64 regs

    auto load_stage = [&](int it) {
        const uint32_t sbase = sm_tiles + (it % STAGES) * STAGE;
        const int k0 = it * BK;
        #pragma unroll
        for (int u = 0; u < TASKS / THR_; ++u) {
            int q = tid + u * THR_;
            if (q < BM * 8) {
                int row = q >> 3, c = q & 7;
                CP_ASYNC16(sbase + SWZ((uint32_t)(row * 128 + c * 16)),
                           A + (size_t)(m0 + row) * K + k0 + c * 8);
            } else {
                int qb = q - BM * 8;
                int row = qb >> 3, c = qb & 7;
                CP_ASYNC16(sbase + STAGE_A + SWZ((uint32_t)(row * 128 + c * 16)),
                           Bp + (size_t)(n0 + row) * K + k0 + c * 8);
            }
        }
    };

    // Prologue: stages 0,1
    load_stage(0); CP_COMMIT();
    load_stage(1); CP_COMMIT();

    #pragma unroll 1
    for (int it = 0; it < NIT; ++it) {
        CP_WAIT(STAGES - 2);
        __syncthreads();       // stage `it` resident AND all warps done with MMA(it-1)

        // Prefetch stage it+2 into buffer (it+2)%3 == (it-1)%3 — safe: all
        // warps finished reading it at the barrier above. Overlaps MMA below.
        if (it + STAGES - 1 < NIT) load_stage(it + STAGES - 1);
        CP_COMMIT();

        const uint32_t sA = sm_tiles + (it % STAGES) * STAGE;
        const uint32_t sB = sA + STAGE_A;

        #pragma unroll
        for (int ks = 0; ks < BK / 16; ++ks) {
            uint32_t af[4][4], bf[2][4];
            #pragma unroll
            for (int i = 0; i < 4; ++i)
                LDMATRIX_X4(af[i][0], af[i][1], af[i][2], af[i][3],
                            sA + SWZ(aOffBase + (uint32_t)(i * 16 * 128 + ks * 32)));
            #pragma unroll
            for (int jj = 0; jj < 2; ++jj)
                LDMATRIX_X4(bf[jj][0], bf[jj][1], bf[jj][2], bf[jj][3],
                            sB + SWZ(bOffBase + (uint32_t)(jj * 16 * 128 + ks * 32)));
            #pragma unroll
            for (int i = 0; i < 4; ++i)
                #pragma unroll
                for (int j = 0; j < 4; ++j)
                    MMA_16816(acc[i][j], af[i], bf[j >> 1][(j & 1)], bf[j >> 1][(j & 1) + 2]);
        }
        // no trailing barrier: next iteration's leading barrier provides it
    }

    // Epilogue
    const int rBase = m0 + wm * 64 + (lane >> 2);
    const int cBase = n0 + wn * 32 + (lane & 3) * 2;
    #pragma unroll
    for (int i = 0; i < 4; ++i) {
        const int r = rBase + i * 16;
        #pragma unroll
        for (int j = 0; j < 4; ++j) {
            const int c = cBase + j * 8;
            if (EPI == 1) {
                *(__half2*)&g_H[(size_t)r * S_CAT + c] =
                    __floats2half2_rn(acc[i][j][0], acc[i][j][1]);
                *(__half2*)&g_H[(size_t)(r + 8) * S_CAT + c] =
                    __floats2half2_rn(acc[i][j][2], acc[i][j][3]);
            } else {
                const float b0 = bias[c], b1 = bias[c + 1];
                float2 v0 = make_float2(acc[i][j][0] + b0, acc[i][j][1] + b1);
                float2 v1 = make_float2(acc[i][j][2] + b0, acc[i][j][3] + b1);
                *(float2*)&out[(size_t)r * DOUT + c] = v0;
                *(float2*)&out[(size_t)(r + 8) * DOUT + c] = v1;
            }
        }
    }
}

// GEMM1: 128x128 tile, 256 thr, 2 CTAs/SM.  smem = 3*32KB = 96KB.
#define G1_SMEM (STAGES * (BM * 128 + 128 * 128))
// GEMM2: 128x256 tile, 512 thr, 1 CTA/SM.   smem = 3*48KB = 144KB.
#define G2_SMEM (STAGES * (BM * 128 + 256 * 128))

// ---------------------------------------------------------------------------
// Launch
// ---------------------------------------------------------------------------
extern "C" void kernel_launch(void* const* d_in, const int* in_sizes, int n_in,
                              void* d_out, int out_size) {
    const float* x    = (const float*)d_in[0];
    const float* V    = (const float*)d_in[1];
    const float* U    = (const float*)d_in[2];
    const float* v1   = (const float*)d_in[3];
    const float* v2   = (const float*)d_in[4];
    const float* u1   = (const float*)d_in[5];
    const float* u2   = (const float*)d_in[6];
    const float* V_R  = (const float*)d_in[7];
    const float* U_R  = (const float*)d_in[8];
    const float* v1_R = (const float*)d_in[9];
    const float* v2_R = (const float*)d_in[10];
    const float* u1_R = (const float*)d_in[11];
    const float* u2_R = (const float*)d_in[12];
    const float* bias = (const float*)d_in[13];
    float* out = (float*)d_out;

    cudaFuncSetAttribute((const void*)gemm_kernel<DIN, 1, 128, 256, 2>,
                         cudaFuncAttributeMaxDynamicSharedMemorySize, G1_SMEM);
    cudaFuncSetAttribute((const void*)gemm_kernel<S_CAT, 2, 256, 512, 1>,
                         cudaFuncAttributeMaxDynamicSharedMemorySize, G2_SMEM);

    // Prep
    prep_x_kernel<<<(int)((size_t)N_TOK * DIN / 4 / 256), 256>>>((const float4*)x);
    prep_B1_kernel<<<(S_CAT * DIN) / 256, 256>>>(V, V_R, v2, v2_R, v1, v1_R, u2, u2_R);
    prep_B2_kernel<<<(DOUT * S_CAT) / 256, 256>>>(U, U_R, u1, u1_R);

    // GEMM1: H = fp16(x) @ B1^T   grid (4, 64) = 256 CTAs, 2/SM
    gemm_kernel<DIN, 1, 128, 256, 2>
        <<<dim3(S_CAT / 128, N_TOK / BM), 256, G1_SMEM>>>(nullptr, nullptr);

    // GEMM2: y = H @ B2^T + bias  grid (16, 64) = 1024 CTAs, 512 thr
    gemm_kernel<S_CAT, 2, 256, 512, 1>
        <<<dim3(DOUT / 256, N_TOK / BM), 512, G2_SMEM>>>(out, bias);
}